// round 1
// baseline (speedup 1.0000x reference)
#include <cuda_runtime.h>
#include <cuda_bf16.h>
#include <math.h>

// Problem constants
#define BB 32
#define SS 256
#define EE 768
#define HH_ 12
#define DH 64
#define LL 2
#define FF_ 2048
#define MM (BB*SS)          // 8192 tokens
#define NEGV (-1e30f)
#define KEEP_HIST 64
#define KEEP_TGT 63

// ---------------- scratch (device globals; no allocation allowed) ----------------
__device__ float g_x[MM*EE];        // hidden state
__device__ float g_qkv[MM*3*EE];    // qkv projections
__device__ float g_attn[MM*EE];     // attention output / dense output reuse
__device__ float g_y[MM*EE];        // projection temp
__device__ float g_h[MM*FF_];       // FFN hidden
__device__ float g_sc[(size_t)BB*HH_*SS*SS]; // attention scores
__device__ float g_cos[MM];

// ---------------- reductions ----------------
__device__ __forceinline__ float warp_sum(float v) {
    #pragma unroll
    for (int o = 16; o; o >>= 1) v += __shfl_xor_sync(0xffffffffu, v, o);
    return v;
}
__device__ __forceinline__ float block_sum(float v, float* red) {
    int lane = threadIdx.x & 31, w = threadIdx.x >> 5;
    v = warp_sum(v);
    if (lane == 0) red[w] = v;
    __syncthreads();
    if (w == 0) {
        float x = (lane < (int)(blockDim.x >> 5)) ? red[lane] : 0.f;
        x = warp_sum(x);
        if (lane == 0) red[0] = x;
    }
    __syncthreads();
    float r = red[0];
    __syncthreads();
    return r;
}

// ---------------- generic tiled GEMM ----------------
// EPI: 0 none, 1 relu, 2 tanh
// TB : 0 -> C[m,n] = sum_k A[m,k] * B[n*ldb + k]   (B is [N,K], "NT")
//      1 -> C[m,n] = sum_k A[m,k] * B[k*ldb + n]   (B is [K,N], "NN")
// Batched via blockIdx.z; z split as zo = z/HH, zi = z%HH with per-matrix strides.
template<int EPI, int TB>
__global__ __launch_bounds__(256) void gemm_k(
    const float* __restrict__ A, const float* __restrict__ Bm,
    const float* __restrict__ bias, float* __restrict__ C,
    int M, int N, int K, int lda, int ldb, int ldc,
    long long saO, long long saI, long long sbO, long long sbI,
    long long scO, long long scI, int HHd)
{
    __shared__ __align__(16) float As[16][64];
    __shared__ __align__(16) float Bs[16][64];

    int z  = blockIdx.z;
    int zo = z / HHd, zi = z - zo * HHd;
    A  += zo * saO + zi * saI;
    Bm += zo * sbO + zi * sbI;
    C  += zo * scO + zi * scI;

    int tid = threadIdx.x;
    int tx = tid & 15, ty = tid >> 4;
    int m0 = blockIdx.y * 64, n0 = blockIdx.x * 64;
    int lr = tid >> 2, lc = (tid & 3) << 2;      // 64x16 tile loader (transpose)
    int br = tid >> 4, bc = (tid & 15) << 2;     // 16x64 tile loader (direct)

    float acc[4][4] = {};

    for (int k0 = 0; k0 < K; k0 += 16) {
        float4 av = *(const float4*)(A + (size_t)(m0 + lr) * lda + k0 + lc);
        As[lc + 0][lr] = av.x; As[lc + 1][lr] = av.y;
        As[lc + 2][lr] = av.z; As[lc + 3][lr] = av.w;
        if (TB == 0) {
            float4 bv = *(const float4*)(Bm + (size_t)(n0 + lr) * ldb + k0 + lc);
            Bs[lc + 0][lr] = bv.x; Bs[lc + 1][lr] = bv.y;
            Bs[lc + 2][lr] = bv.z; Bs[lc + 3][lr] = bv.w;
        } else {
            float4 bv = *(const float4*)(Bm + (size_t)(k0 + br) * ldb + n0 + bc);
            *(float4*)&Bs[br][bc] = bv;
        }
        __syncthreads();
        #pragma unroll
        for (int kk = 0; kk < 16; kk++) {
            float4 a = *(const float4*)&As[kk][ty << 2];
            float4 b = *(const float4*)&Bs[kk][tx << 2];
            acc[0][0] += a.x * b.x; acc[0][1] += a.x * b.y; acc[0][2] += a.x * b.z; acc[0][3] += a.x * b.w;
            acc[1][0] += a.y * b.x; acc[1][1] += a.y * b.y; acc[1][2] += a.y * b.z; acc[1][3] += a.y * b.w;
            acc[2][0] += a.z * b.x; acc[2][1] += a.z * b.y; acc[2][2] += a.z * b.z; acc[2][3] += a.z * b.w;
            acc[3][0] += a.w * b.x; acc[3][1] += a.w * b.y; acc[3][2] += a.w * b.z; acc[3][3] += a.w * b.w;
        }
        __syncthreads();
    }

    float4 bb = make_float4(0.f, 0.f, 0.f, 0.f);
    if (bias) bb = *(const float4*)(bias + n0 + (tx << 2));
    #pragma unroll
    for (int i = 0; i < 4; i++) {
        int row = m0 + (ty << 2) + i;
        float4 v;
        v.x = acc[i][0] + bb.x; v.y = acc[i][1] + bb.y;
        v.z = acc[i][2] + bb.z; v.w = acc[i][3] + bb.w;
        if (EPI == 1) { v.x = fmaxf(v.x, 0.f); v.y = fmaxf(v.y, 0.f); v.z = fmaxf(v.z, 0.f); v.w = fmaxf(v.w, 0.f); }
        if (EPI == 2) { v.x = tanhf(v.x); v.y = tanhf(v.y); v.z = tanhf(v.z); v.w = tanhf(v.w); }
        *(float4*)(C + (size_t)row * ldc + n0 + (tx << 2)) = v;
    }
}

// ---------------- embed + LN ----------------
__global__ __launch_bounds__(256) void embed_ln_k(
    const float* __restrict__ tok, const int* __restrict__ pos,
    const int* __restrict__ typ, const float* __restrict__ pe,
    const float* __restrict__ temb, const float* __restrict__ w,
    const float* __restrict__ b, float* __restrict__ out)
{
    __shared__ float red[32];
    int t = blockIdx.x;
    int p = pos[t], ty = typ[t];
    int e0 = threadIdx.x;
    float v[3];
    #pragma unroll
    for (int i = 0; i < 3; i++) {
        int e = e0 + i * 256;
        v[i] = tok[(size_t)t * EE + e] + pe[(size_t)p * EE + e] + temb[(size_t)ty * EE + e];
    }
    float mean = block_sum(v[0] + v[1] + v[2], red) * (1.f / 768.f);
    float d[3]; float ss = 0.f;
    #pragma unroll
    for (int i = 0; i < 3; i++) { d[i] = v[i] - mean; ss += d[i] * d[i]; }
    float var = block_sum(ss, red) * (1.f / 768.f);
    float inv = rsqrtf(var + 1e-5f);
    #pragma unroll
    for (int i = 0; i < 3; i++) {
        int e = e0 + i * 256;
        out[(size_t)t * EE + e] = d[i] * inv * w[e] + b[e];
    }
}

// ---------------- (x + r) -> LN ----------------
__global__ __launch_bounds__(256) void add_ln_k(
    const float* __restrict__ x, const float* __restrict__ r,
    const float* __restrict__ w, const float* __restrict__ b,
    float* __restrict__ out)
{
    __shared__ float red[32];
    int t = blockIdx.x;
    int e0 = threadIdx.x;
    float v[3];
    #pragma unroll
    for (int i = 0; i < 3; i++) {
        int e = e0 + i * 256;
        float xv = x[(size_t)t * EE + e];
        if (r) xv += r[(size_t)t * EE + e];
        v[i] = xv;
    }
    float mean = block_sum(v[0] + v[1] + v[2], red) * (1.f / 768.f);
    float d[3]; float ss = 0.f;
    #pragma unroll
    for (int i = 0; i < 3; i++) { d[i] = v[i] - mean; ss += d[i] * d[i]; }
    float var = block_sum(ss, red) * (1.f / 768.f);
    float inv = rsqrtf(var + 1e-5f);
    #pragma unroll
    for (int i = 0; i < 3; i++) {
        int e = e0 + i * 256;
        out[(size_t)t * EE + e] = d[i] * inv * w[e] + b[e];
    }
}

// ---------------- masked softmax over score rows ----------------
// rows = B*H*S ; one warp per row of length S=256
__global__ __launch_bounds__(256) void softmax_k(
    float* __restrict__ sc, const unsigned char* __restrict__ mask)
{
    int w = threadIdx.x >> 5, lane = threadIdx.x & 31;
    long long r = (long long)blockIdx.x * 8 + w;
    int bh = (int)(r >> 8);
    int b = bh / HH_;
    float* row = sc + r * SS;
    const unsigned char* mrow = mask + (size_t)b * SS;
    float v[8];
    #pragma unroll
    for (int j = 0; j < 8; j++) {
        int k = lane + 32 * j;
        float x = row[k] * 0.125f;           // 1/sqrt(64)
        v[j] = mrow[k] ? NEGV : x;
    }
    float m = v[0];
    #pragma unroll
    for (int j = 1; j < 8; j++) m = fmaxf(m, v[j]);
    #pragma unroll
    for (int o = 16; o; o >>= 1) m = fmaxf(m, __shfl_xor_sync(0xffffffffu, m, o));
    float sum = 0.f;
    #pragma unroll
    for (int j = 0; j < 8; j++) { v[j] = __expf(v[j] - m); sum += v[j]; }
    sum = warp_sum(sum);
    float inv = 1.f / sum;
    #pragma unroll
    for (int j = 0; j < 8; j++) row[lane + 32 * j] = v[j] * inv;
}

// ---------------- cosine similarity per token ----------------
__global__ __launch_bounds__(256) void cos_k(
    const float* __restrict__ a, const float* __restrict__ bten, float* __restrict__ out)
{
    int w = threadIdx.x >> 5, lane = threadIdx.x & 31;
    int t = blockIdx.x * 8 + w;
    const float* pa = a + (size_t)t * EE;
    const float* pb = bten + (size_t)t * EE;
    float dot = 0.f, na = 0.f, nb = 0.f;
    for (int i = lane; i < EE; i += 32) {
        float x = pa[i], y = pb[i];
        dot += x * y; na += x * x; nb += y * y;
    }
    dot = warp_sum(dot); na = warp_sum(na); nb = warp_sum(nb);
    if (lane == 0)
        out[t] = dot / fmaxf(sqrtf(na) * sqrtf(nb), 1e-8f);
}

// ---------------- gumbel top-k mask generation ----------------
__global__ __launch_bounds__(256) void maskgen_k(
    const float* __restrict__ cosv, const int* __restrict__ typ,
    const float* __restrict__ gh, const float* __restrict__ gt,
    float* __restrict__ out)
{
    __shared__ float glh[256], glt[256];
    __shared__ float red[32];
    int b = blockIdx.x, s = threadIdx.x;
    int t = typ[b * SS + s];
    float c = cosv[b * SS + s];
    bool hm = (t == 1), tm = (t == 2);
    float eh = hm ? expf(c) : 0.f;
    float et = tm ? expf(c) : 0.f;
    float sh = block_sum(eh, red);
    float st = block_sum(et, red);
    float vh = hm ? (logf(eh / sh) + gh[b * SS + s]) : NEGV;
    float vt = tm ? (logf(1.f - et / st) + gt[b * SS + s]) : NEGV;
    glh[s] = vh; glt[s] = vt;
    __syncthreads();
    int rh = 0, rt = 0;
    for (int j = 0; j < 256; j++) {
        float a = glh[j];
        rh += (a > vh) || (a == vh && j < s);
        float bb2 = glt[j];
        rt += (bb2 > vt) || (bb2 == vt && j < s);
    }
    float o = 0.f;
    if (hm && rh < KEEP_HIST) o += 1.f;
    if (tm && rt < KEEP_TGT)  o += 1.f;
    out[b * SS + s] = o;
}

// ---------------- host launch ----------------
extern "C" void kernel_launch(void* const* d_in, const int* in_sizes, int n_in,
                              void* d_out, int out_size)
{
    const float* tok  = (const float*)d_in[0];
    const unsigned char* amask = (const unsigned char*)d_in[1];
    const int* pos    = (const int*)d_in[2];
    const int* typ    = (const int*)d_in[3];
    const float* gh   = (const float*)d_in[4];
    const float* gt   = (const float*)d_in[5];
    const float* pe   = (const float*)d_in[6];
    const float* temb = (const float*)d_in[7];
    const float* ln_w = (const float*)d_in[8];
    const float* ln_b = (const float*)d_in[9];
    const float* dense_w = (const float*)d_in[10];
    const float* dense_b = (const float*)d_in[11];
    const float* qkv_w = (const float*)d_in[12];
    const float* qkv_b = (const float*)d_in[13];
    const float* out_w = (const float*)d_in[14];
    const float* out_b = (const float*)d_in[15];
    const float* ln1_w = (const float*)d_in[16];
    const float* ln1_b = (const float*)d_in[17];
    const float* lin1_w = (const float*)d_in[18];
    const float* lin1_b = (const float*)d_in[19];
    const float* lin2_w = (const float*)d_in[20];
    const float* lin2_b = (const float*)d_in[21];
    const float* ln2_w = (const float*)d_in[22];
    const float* ln2_b = (const float*)d_in[23];
    float* out = (float*)d_out;

    float *gx, *gqkv, *gattn, *gy, *ghid, *gsc, *gcos;
    cudaGetSymbolAddress((void**)&gx,    g_x);
    cudaGetSymbolAddress((void**)&gqkv,  g_qkv);
    cudaGetSymbolAddress((void**)&gattn, g_attn);
    cudaGetSymbolAddress((void**)&gy,    g_y);
    cudaGetSymbolAddress((void**)&ghid,  g_h);
    cudaGetSymbolAddress((void**)&gsc,   g_sc);
    cudaGetSymbolAddress((void**)&gcos,  g_cos);

    embed_ln_k<<<MM, 256>>>(tok, pos, typ, pe, temb, ln_w, ln_b, gx);

    for (int l = 0; l < LL; l++) {
        // qkv = x @ qkv_w[l]^T + qkv_b[l]
        gemm_k<0,0><<<dim3(36, 128, 1), 256>>>(
            gx, qkv_w + (size_t)l * 3 * EE * EE, qkv_b + (size_t)l * 3 * EE, gqkv,
            MM, 3 * EE, EE, EE, EE, 3 * EE,
            0, 0, 0, 0, 0, 0, 1);

        // scores[b,h,q,k] = q . k  (batched NT, z = b*H + h)
        gemm_k<0,0><<<dim3(4, 4, BB * HH_), 256>>>(
            gqkv, gqkv + EE, nullptr, gsc,
            SS, SS, DH, 3 * EE, 3 * EE, SS,
            (long long)SS * 3 * EE, DH,
            (long long)SS * 3 * EE, DH,
            (long long)HH_ * SS * SS, (long long)SS * SS, HH_);

        softmax_k<<<(BB * HH_ * SS) / 8, 256>>>(gsc, amask);

        // o[b,q,h,d] = P @ V (batched NN)
        gemm_k<0,1><<<dim3(1, 4, BB * HH_), 256>>>(
            gsc, gqkv + 2 * EE, nullptr, gattn,
            SS, DH, SS, SS, 3 * EE, EE,
            (long long)HH_ * SS * SS, (long long)SS * SS,
            (long long)SS * 3 * EE, DH,
            (long long)SS * EE, DH, HH_);

        // out proj
        gemm_k<0,0><<<dim3(12, 128, 1), 256>>>(
            gattn, out_w + (size_t)l * EE * EE, out_b + (size_t)l * EE, gy,
            MM, EE, EE, EE, EE, EE, 0, 0, 0, 0, 0, 0, 1);

        add_ln_k<<<MM, 256>>>(gx, gy, ln1_w + l * EE, ln1_b + l * EE, gx);

        // FFN
        gemm_k<1,0><<<dim3(32, 128, 1), 256>>>(
            gx, lin1_w + (size_t)l * FF_ * EE, lin1_b + (size_t)l * FF_, ghid,
            MM, FF_, EE, EE, EE, FF_, 0, 0, 0, 0, 0, 0, 1);

        gemm_k<0,0><<<dim3(12, 128, 1), 256>>>(
            ghid, lin2_w + (size_t)l * EE * FF_, lin2_b + (size_t)l * EE, gy,
            MM, EE, FF_, FF_, FF_, EE, 0, 0, 0, 0, 0, 0, 1);

        add_ln_k<<<MM, 256>>>(gx, gy, ln2_w + l * EE, ln2_b + l * EE, gx);
    }

    // final LN (no residual)
    add_ln_k<<<MM, 256>>>(gx, nullptr, ln_w, ln_b, gy);

    // dense + tanh  -> reuse g_attn
    gemm_k<2,0><<<dim3(12, 128, 1), 256>>>(
        gy, dense_w, dense_b, gattn,
        MM, EE, EE, EE, EE, EE, 0, 0, 0, 0, 0, 0, 1);

    cos_k<<<MM / 8, 256>>>(tok, gattn, gcos);

    maskgen_k<<<BB, 256>>>(gcos, typ, gh, gt, out);
}